// round 1
// baseline (speedup 1.0000x reference)
#include <cuda_runtime.h>

#define BB 64
#define TT 512
#define DD 1024
#define KK 32
#define BTK (BB*TT*KK)

// scratch (allowed: __device__ globals, no allocation)
__device__ float g_scratch_logits[BTK];
__device__ float g_spart[BB];
__device__ int   g_msum[BB];

// ---------------------------------------------------------------------------
// warp reduction helpers
// ---------------------------------------------------------------------------
__device__ __forceinline__ float warpMaxf(float v) {
#pragma unroll
    for (int o = 16; o > 0; o >>= 1)
        v = fmaxf(v, __shfl_xor_sync(0xffffffffu, v, o));
    return v;
}
__device__ __forceinline__ float warpSumf(float v) {
#pragma unroll
    for (int o = 16; o > 0; o >>= 1)
        v += __shfl_xor_sync(0xffffffffu, v, o);
    return v;
}
__device__ __forceinline__ int warpSumi(int v) {
#pragma unroll
    for (int o = 16; o > 0; o >>= 1)
        v += __shfl_xor_sync(0xffffffffu, v, o);
    return v;
}

// ---------------------------------------------------------------------------
// GEMM: logits[r*32+k] = sum_d V[r*1024+d]*W[k*1024+d] + bias[k]
// Block = 256 threads (8 warps), tile = 64 rows x 32 cols, D chunks of 128.
// Each warp: 8 rows, lane = k column. FFMA-bound (~2 FFMA-instr/cyc/SM).
// ---------------------------------------------------------------------------
__global__ __launch_bounds__(256) void gemm_kernel(
    const float* __restrict__ V, const float* __restrict__ W,
    const float* __restrict__ bias, float* __restrict__ out)
{
    __shared__ float Vs[64][128];
    __shared__ float Ws[32][132];   // pad to 132 floats (528B, 16B aligned rows)

    const int tid  = threadIdx.x;
    const int warp = tid >> 5;
    const int lane = tid & 31;
    const int rowBase = blockIdx.x * 64;

    float acc[8];
    const float bk = bias[lane];
#pragma unroll
    for (int r = 0; r < 8; r++) acc[r] = bk;

    for (int kc = 0; kc < 8; kc++) {
        const int d0 = kc * 128;
        // load V tile: 64 rows x 128 cols = 2048 float4, 8 per thread
#pragma unroll
        for (int p = 0; p < 8; p++) {
            int idx = p * 256 + tid;
            int r  = idx >> 5;
            int c4 = idx & 31;
            float4 v = *(const float4*)&V[(size_t)(rowBase + r) * DD + d0 + c4 * 4];
            *(float4*)&Vs[r][c4 * 4] = v;
        }
        // load W tile: 32 rows x 128 cols = 1024 float4, 4 per thread
#pragma unroll
        for (int p = 0; p < 4; p++) {
            int idx = p * 256 + tid;
            int k  = idx >> 5;
            int c4 = idx & 31;
            float4 w = *(const float4*)&W[(size_t)k * DD + d0 + c4 * 4];
            *(float4*)&Ws[k][c4 * 4] = w;
        }
        __syncthreads();

#pragma unroll 8
        for (int dd = 0; dd < 128; dd += 4) {
            float4 w = *(const float4*)&Ws[lane][dd];
#pragma unroll
            for (int r = 0; r < 8; r++) {
                float4 v = *(const float4*)&Vs[warp * 8 + r][dd];
                acc[r] = fmaf(w.x, v.x, acc[r]);
                acc[r] = fmaf(w.y, v.y, acc[r]);
                acc[r] = fmaf(w.z, v.z, acc[r]);
                acc[r] = fmaf(w.w, v.w, acc[r]);
            }
        }
        __syncthreads();
    }

#pragma unroll
    for (int r = 0; r < 8; r++)
        out[(size_t)(rowBase + warp * 8 + r) * KK + lane] = acc[r];
}

// ---------------------------------------------------------------------------
// CRF forward + score. One warp per batch; lane j = state j.
// Probability-space recurrence with periodic renormalization:
//   a ~ exp(alpha - c),  step: a'[j] = (sum_i a[i]*E[i][j]) * exp(lg[j]-maxlg)
//   c' = c + maxlg ; renorm (divide by warp-max, add log to c) every 8 steps.
// ---------------------------------------------------------------------------
__global__ __launch_bounds__(32) void crf_kernel(
    const float* __restrict__ L,       // logits [B,T,K]
    const int*   __restrict__ mask,    // [B,T]
    const int*   __restrict__ targets, // [B,T]
    const float* __restrict__ trans,   // [K,K]
    const float* __restrict__ startT,  // [K]
    const float* __restrict__ endT)    // [K]
{
    const int b = blockIdx.x;
    const int j = threadIdx.x;
    const unsigned FULL = 0xffffffffu;

    // E column j in registers: e[i] = exp(trans[i][j])
    float e[32];
#pragma unroll
    for (int i = 0; i < 32; i++) e[i] = __expf(trans[i * KK + j]);

    const float* Lb = L + (size_t)b * TT * KK;
    const int*   mb = mask + (size_t)b * TT;

    // ---- init (t = 0) ----
    float s  = startT[j] + Lb[j];
    float mm = warpMaxf(s);
    float a  = __expf(s - mm);
    float c  = mm;   // uniform across lanes

    float lg_cur = Lb[KK + j];
    int   m_cur  = mb[1];

    for (int t = 1; t < TT; t++) {
        // prefetch next step
        float lg_next = 0.f; int m_next = 0;
        if (t + 1 < TT) {
            lg_next = Lb[(size_t)(t + 1) * KK + j];
            m_next  = mb[t + 1];
        }

        // logit max (independent of dot chain -> overlaps)
        float mL = warpMaxf(lg_cur);
        float g  = __expf(lg_cur - mL);

        // dot = sum_i a[i] * e[i]  via shfl broadcast
        float av = a;
        float acc0 = 0.f, acc1 = 0.f, acc2 = 0.f, acc3 = 0.f;
#pragma unroll
        for (int i = 0; i < 32; i += 4) {
            float a0 = __shfl_sync(FULL, av, i);
            float a1 = __shfl_sync(FULL, av, i + 1);
            float a2 = __shfl_sync(FULL, av, i + 2);
            float a3 = __shfl_sync(FULL, av, i + 3);
            acc0 = fmaf(a0, e[i],     acc0);
            acc1 = fmaf(a1, e[i + 1], acc1);
            acc2 = fmaf(a2, e[i + 2], acc2);
            acc3 = fmaf(a3, e[i + 3], acc3);
        }
        float dot = (acc0 + acc1) + (acc2 + acc3);

        if (m_cur > 0) { a = dot * g; c += mL; }

        // periodic renormalization (semantically neutral, keeps fp32 range)
        if ((t & 7) == 7) {
            float Mx = warpMaxf(a);
            a = a / Mx;
            c += __logf(Mx);
        }

        lg_cur = lg_next; m_cur = m_next;
    }

    // partition = c + log(sum_j a_j * exp(end_j))
    float pe = a * __expf(endT[j]);
    float S  = warpSumf(pe);
    float partition = c + __logf(S);

    // ---- gold path score ----
    float emit_s = 0.f, trans_s = 0.f;
    int msum = 0;
    for (int t = j; t < TT; t += 32) {
        int tg = targets[(size_t)b * TT + t];
        int mk = mb[t];
        float em = Lb[(size_t)t * KK + tg];
        emit_s += em * (float)mk;                 // covers t=0..T-1 incl. last
        if (t >= 1) {
            int tgp = targets[(size_t)b * TT + t - 1];
            trans_s += trans[tgp * KK + tg] * (float)mk;
        }
        msum += mk;
    }
    emit_s  = warpSumf(emit_s);
    trans_s = warpSumf(trans_s);
    msum    = warpSumi(msum);

    if (j == 0) {
        int last = msum - 1;
        int t0 = targets[(size_t)b * TT];
        int tl = targets[(size_t)b * TT + last];
        float score = startT[t0] + emit_s + trans_s + endT[tl];
        g_spart[b] = score - partition;
        g_msum[b]  = msum;
    }
}

// ---------------------------------------------------------------------------
// final: loss = -sum_b (score_b - partition_b) / sum(mask)
// ---------------------------------------------------------------------------
__global__ __launch_bounds__(32) void finish_kernel(float* __restrict__ out,
                                                    int writeLoss)
{
    const int j = threadIdx.x;
    float sp = g_spart[j] + g_spart[j + 32];
    int   ms = g_msum[j]  + g_msum[j + 32];
    sp = warpSumf(sp);
    ms = warpSumi(ms);
    if (j == 0 && writeLoss) out[0] = -sp / (float)ms;
}

// ---------------------------------------------------------------------------
extern "C" void kernel_launch(void* const* d_in, const int* in_sizes, int n_in,
                              void* d_out, int out_size)
{
    const float* V       = (const float*)d_in[0];
    const int*   mask    = (const int*)  d_in[1];
    const int*   targets = (const int*)  d_in[2];
    const float* W       = (const float*)d_in[3];
    const float* bias    = (const float*)d_in[4];
    const float* trans   = (const float*)d_in[5];
    const float* startT  = (const float*)d_in[6];
    const float* endT    = (const float*)d_in[7];
    float* out = (float*)d_out;

    const int loff = out_size - BTK;   // expected 1: (loss, logits) concat
    float* logits;
    if (loff >= 0) {
        logits = out + loff;
    } else {
        void* p = nullptr;
        cudaGetSymbolAddress(&p, g_scratch_logits);
        logits = (float*)p;
    }

    gemm_kernel<<<(BB * TT) / 64, 256>>>(V, W, bias, logits);
    crf_kernel<<<BB, 32>>>(logits, mask, targets, trans, startT, endT);
    finish_kernel<<<1, 32>>>(out, (loff >= 1) ? 1 : 0);
}

// round 4
// speedup vs baseline: 1.2843x; 1.2843x over previous
#include <cuda_runtime.h>
#include <cstdint>

#define BB 64
#define TT 512
#define DD 1024
#define KK 32
#define BTK (BB*TT*KK)

// scratch (allowed: __device__ globals, no allocation) — 16B-aligned logits copy
__device__ __align__(16) float g_scratch_logits[BTK];
__device__ float g_spart[BB];
__device__ int   g_msum[BB];

// ---------------------------------------------------------------------------
// helpers
// ---------------------------------------------------------------------------
__device__ __forceinline__ void cpa16(void* dst, const void* src) {
    unsigned s = (unsigned)__cvta_generic_to_shared(dst);
    asm volatile("cp.async.cg.shared.global [%0], [%1], 16;\n" :: "r"(s), "l"(src));
}
__device__ __forceinline__ void cpa_commit() { asm volatile("cp.async.commit_group;\n"); }
template<int N> __device__ __forceinline__ void cpa_wait() {
    asm volatile("cp.async.wait_group %0;\n" :: "n"(N));
}

__device__ __forceinline__ float warpMaxf(float v) {
#pragma unroll
    for (int o = 16; o > 0; o >>= 1)
        v = fmaxf(v, __shfl_xor_sync(0xffffffffu, v, o));
    return v;
}
__device__ __forceinline__ float warpSumf(float v) {
#pragma unroll
    for (int o = 16; o > 0; o >>= 1)
        v += __shfl_xor_sync(0xffffffffu, v, o);
    return v;
}
__device__ __forceinline__ int warpSumi(int v) {
#pragma unroll
    for (int o = 16; o > 0; o >>= 1)
        v += __shfl_xor_sync(0xffffffffu, v, o);
    return v;
}

// ---------------------------------------------------------------------------
// GEMM: logits[r*32+k] = sum_d V[r,d]*W[k,d] + bias[k]
// 256 threads, tile 64 rows x 32 cols, D chunks of 64, cp.async double-buffer.
// Writes to the (possibly unaligned) harness output AND the aligned scratch.
// ---------------------------------------------------------------------------
__global__ __launch_bounds__(256, 4) void gemm_kernel(
    const float* __restrict__ V, const float* __restrict__ W,
    const float* __restrict__ bias, float* __restrict__ out,
    float* __restrict__ outAligned, int dualStore)
{
    __shared__ float Vs[2][64][64];
    __shared__ float Ws[2][32][68];   // 68 ≡ 4 (mod 32): phase-conflict-free LDS.128

    const int tid  = threadIdx.x;
    const int warp = tid >> 5;
    const int lane = tid & 31;
    const int rowBase = blockIdx.x * 64;

    float acc[8];
    const float bk = bias[lane];
#pragma unroll
    for (int r = 0; r < 8; r++) acc[r] = bk;

    auto loadChunk = [&](int buf, int kc) {
        const int d0 = kc * 64;
#pragma unroll
        for (int p = 0; p < 4; p++) {                 // V: 1024 float4
            int idx = p * 256 + tid;
            int r = idx >> 4, c4 = idx & 15;
            cpa16(&Vs[buf][r][c4 * 4], &V[(size_t)(rowBase + r) * DD + d0 + c4 * 4]);
        }
#pragma unroll
        for (int p = 0; p < 2; p++) {                 // W: 512 float4
            int idx = p * 256 + tid;
            int k = idx >> 4, c4 = idx & 15;
            cpa16(&Ws[buf][k][c4 * 4], &W[(size_t)k * DD + d0 + c4 * 4]);
        }
        cpa_commit();
    };

    loadChunk(0, 0);
    loadChunk(1, 1);

    for (int kc = 0; kc < 16; kc++) {
        const int buf = kc & 1;
        cpa_wait<1>();
        __syncthreads();

#pragma unroll 4
        for (int dd = 0; dd < 64; dd += 4) {
            float4 w = *(const float4*)&Ws[buf][lane][dd];
#pragma unroll
            for (int r = 0; r < 8; r++) {
                float4 v = *(const float4*)&Vs[buf][warp * 8 + r][dd];   // broadcast
                acc[r] = fmaf(w.x, v.x, acc[r]);
                acc[r] = fmaf(w.y, v.y, acc[r]);
                acc[r] = fmaf(w.z, v.z, acc[r]);
                acc[r] = fmaf(w.w, v.w, acc[r]);
            }
        }
        __syncthreads();
        if (kc + 2 < 16) loadChunk(buf, kc + 2);
    }

#pragma unroll
    for (int r = 0; r < 8; r++) {
        size_t idx = (size_t)(rowBase + warp * 8 + r) * KK + lane;
        outAligned[idx] = acc[r];
        if (dualStore) out[idx] = acc[r];
    }
}

// ---------------------------------------------------------------------------
// CRF forward + gold-path score. One warp per batch; lane j = state j.
// Scaled-probability recurrence, logits staged via cp.async in 16-step chunks,
// per-chunk precompute of g[s]=exp(lg-max lg), renorm once per chunk.
// L must be 16B aligned (the scratch copy).
// ---------------------------------------------------------------------------
__global__ __launch_bounds__(32) void crf_kernel(
    const float* __restrict__ L,       // logits [B,T,K] (aligned)
    const int*   __restrict__ mask,    // [B,T]
    const int*   __restrict__ targets, // [B,T]
    const float* __restrict__ trans,   // [K,K]
    const float* __restrict__ startT,  // [K]
    const float* __restrict__ endT)    // [K]
{
    __shared__ float Ls[2][16 * 32];   // 2 x 2KB
    const int b = blockIdx.x;
    const int j = threadIdx.x;
    const unsigned FULL = 0xffffffffu;

    // E column j in registers
    float e[32];
#pragma unroll
    for (int i = 0; i < 32; i++) e[i] = __expf(trans[i * KK + j]);

    const float* Lb = L + (size_t)b * TT * KK;
    const int*   mb = mask + (size_t)b * TT;

    // mask bitmask: 512 bits replicated in every lane (ballot)
    unsigned mbits[16];
#pragma unroll
    for (int w = 0; w < 16; w++) {
        int v = mb[w * 32 + j];
        mbits[w] = __ballot_sync(FULL, v != 0);
    }

    auto loadChunk = [&](int buf, int c) {
        const float* src = Lb + (size_t)c * 16 * KK;
#pragma unroll
        for (int q = 0; q < 4; q++) {
            int idx = q * 32 + j;              // 128 float4 per chunk
            cpa16(&Ls[buf][idx * 4], src + idx * 4);
        }
        cpa_commit();
    };

    loadChunk(0, 0);
    loadChunk(1, 1);

    float a = 0.f, cl = 0.f;

    for (int c = 0; c < 32; c++) {
        const int buf = c & 1;
        cpa_wait<1>();
        __syncwarp();

        // ---- precompute g[s], mLs[s] for this chunk (16 independent trees) ----
        float g[16], mLs[16], lgraw0 = 0.f;
#pragma unroll
        for (int s = 0; s < 16; s++) {
            float lg = Ls[buf][s * 32 + j];
            if (s == 0) lgraw0 = lg;
            float mL = warpMaxf(lg);
            g[s]   = __expf(lg - mL);
            mLs[s] = mL;
        }
        __syncwarp();
        if (c + 2 < 32) loadChunk(buf, c + 2);   // overwrite safe: all reads done

        // ---- scan ----
        const unsigned bits = mbits[c >> 1] >> ((c & 1) * 16);   // 16 bits of this chunk

        auto step = [&](int s) {
            float av = a;
            float a0 = 0.f, a1 = 0.f, a2 = 0.f, a3 = 0.f;
            float a4 = 0.f, a5 = 0.f, a6 = 0.f, a7 = 0.f;
#pragma unroll
            for (int i = 0; i < 4; i++) {
                a0 = fmaf(__shfl_sync(FULL, av, i * 8 + 0), e[i * 8 + 0], a0);
                a1 = fmaf(__shfl_sync(FULL, av, i * 8 + 1), e[i * 8 + 1], a1);
                a2 = fmaf(__shfl_sync(FULL, av, i * 8 + 2), e[i * 8 + 2], a2);
                a3 = fmaf(__shfl_sync(FULL, av, i * 8 + 3), e[i * 8 + 3], a3);
                a4 = fmaf(__shfl_sync(FULL, av, i * 8 + 4), e[i * 8 + 4], a4);
                a5 = fmaf(__shfl_sync(FULL, av, i * 8 + 5), e[i * 8 + 5], a5);
                a6 = fmaf(__shfl_sync(FULL, av, i * 8 + 6), e[i * 8 + 6], a6);
                a7 = fmaf(__shfl_sync(FULL, av, i * 8 + 7), e[i * 8 + 7], a7);
            }
            float dot = ((a0 + a1) + (a2 + a3)) + ((a4 + a5) + (a6 + a7));
            if ((bits >> s) & 1u) { a = dot * g[s]; cl += mLs[s]; }
        };

        if (c == 0) {
            // init t = 0
            float s0v = startT[j] + lgraw0;
            float mm = warpMaxf(s0v);
            a  = __expf(s0v - mm);
            cl = mm;
#pragma unroll
            for (int s = 1; s < 16; s++) step(s);
        } else {
#pragma unroll
            for (int s = 0; s < 16; s++) step(s);
        }

        // ---- renorm once per 16 steps ----
        float Mx = warpMaxf(a);
        a = __fdividef(a, Mx);
        cl += __logf(Mx);
    }

    // partition = cl + log(sum_j a_j * exp(end_j))
    float pe = a * __expf(endT[j]);
    float S  = warpSumf(pe);
    float partition = cl + __logf(S);

    // ---- gold path score ----
    float emit_s = 0.f, trans_s = 0.f;
    int msum = 0;
    for (int t = j; t < TT; t += 32) {
        int tg = targets[(size_t)b * TT + t];
        int mk = mb[t];
        float em = Lb[(size_t)t * KK + tg];
        emit_s += em * (float)mk;
        if (t >= 1) {
            int tgp = targets[(size_t)b * TT + t - 1];
            trans_s += trans[tgp * KK + tg] * (float)mk;
        }
        msum += mk;
    }
    emit_s  = warpSumf(emit_s);
    trans_s = warpSumf(trans_s);
    msum    = warpSumi(msum);

    if (j == 0) {
        int last = msum - 1;
        int t0 = targets[(size_t)b * TT];
        int tl = targets[(size_t)b * TT + last];
        float score = startT[t0] + emit_s + trans_s + endT[tl];
        g_spart[b] = score - partition;
        g_msum[b]  = msum;
    }
}

// ---------------------------------------------------------------------------
__global__ __launch_bounds__(32) void finish_kernel(float* __restrict__ out,
                                                    int writeLoss)
{
    const int j = threadIdx.x;
    float sp = g_spart[j] + g_spart[j + 32];
    int   ms = g_msum[j]  + g_msum[j + 32];
    sp = warpSumf(sp);
    ms = warpSumi(ms);
    if (j == 0 && writeLoss) out[0] = -sp / (float)ms;
}

// ---------------------------------------------------------------------------
extern "C" void kernel_launch(void* const* d_in, const int* in_sizes, int n_in,
                              void* d_out, int out_size)
{
    const float* V       = (const float*)d_in[0];
    const int*   mask    = (const int*)  d_in[1];
    const int*   targets = (const int*)  d_in[2];
    const float* W       = (const float*)d_in[3];
    const float* bias    = (const float*)d_in[4];
    const float* trans   = (const float*)d_in[5];
    const float* startT  = (const float*)d_in[6];
    const float* endT    = (const float*)d_in[7];
    float* out = (float*)d_out;

    void* p = nullptr;
    cudaGetSymbolAddress(&p, g_scratch_logits);
    float* scratch = (float*)p;

    const int loff = out_size - BTK;   // (loss, logits) concat
    float* outLogits;
    int dualStore;
    if (loff >= 0) {
        outLogits = out + loff;
        // if the harness slot happens to be 16B aligned, write it directly once
        if ((((uintptr_t)outLogits) & 15u) == 0) {
            scratch = outLogits;            // aligned: single store stream
            dualStore = 0;
        } else {
            dualStore = 1;                  // unaligned: scratch + harness copy
        }
    } else {
        outLogits = scratch;                // logits not in output at all
        dualStore = 0;
    }

    gemm_kernel<<<(BB * TT) / 64, 256>>>(V, W, bias, outLogits, scratch, dualStore);
    crf_kernel<<<BB, 32>>>(scratch, mask, targets, trans, startT, endT);
    finish_kernel<<<1, 32>>>(out, (loff >= 1) ? 1 : 0);
}

// round 5
// speedup vs baseline: 1.6820x; 1.3096x over previous
#include <cuda_runtime.h>
#include <cstdint>

#define BB 64
#define TT 512
#define DD 1024
#define KK 32
#define BTK (BB*TT*KK)

// scratch (allowed: __device__ globals, no allocation) — 16B-aligned logits copy
__device__ __align__(16) float g_scratch_logits[BTK];
__device__ float g_spart[BB];
__device__ int   g_msum[BB];

// ---------------------------------------------------------------------------
// helpers
// ---------------------------------------------------------------------------
__device__ __forceinline__ void cpa16(void* dst, const void* src) {
    unsigned s = (unsigned)__cvta_generic_to_shared(dst);
    asm volatile("cp.async.cg.shared.global [%0], [%1], 16;\n" :: "r"(s), "l"(src));
}
__device__ __forceinline__ void cpa_commit() { asm volatile("cp.async.commit_group;\n"); }
template<int N> __device__ __forceinline__ void cpa_wait() {
    asm volatile("cp.async.wait_group %0;\n" :: "n"(N));
}

typedef unsigned long long ull;
__device__ __forceinline__ ull fma2(ull a, ull b, ull c) {
    ull d; asm("fma.rn.f32x2 %0, %1, %2, %3;" : "=l"(d) : "l"(a), "l"(b), "l"(c));
    return d;
}
__device__ __forceinline__ ull add2(ull a, ull b) {
    ull d; asm("add.rn.f32x2 %0, %1, %2;" : "=l"(d) : "l"(a), "l"(b));
    return d;
}
__device__ __forceinline__ ull pack2(float lo, float hi) {
    ull d; asm("mov.b64 %0, {%1, %2};" : "=l"(d) : "f"(lo), "f"(hi));
    return d;
}
__device__ __forceinline__ float2 unpack2(ull v) {
    float2 f; asm("mov.b64 {%0, %1}, %2;" : "=f"(f.x), "=f"(f.y) : "l"(v));
    return f;
}

__device__ __forceinline__ float warpMaxf(float v) {
#pragma unroll
    for (int o = 16; o > 0; o >>= 1)
        v = fmaxf(v, __shfl_xor_sync(0xffffffffu, v, o));
    return v;
}
__device__ __forceinline__ float warpSumf(float v) {
#pragma unroll
    for (int o = 16; o > 0; o >>= 1)
        v += __shfl_xor_sync(0xffffffffu, v, o);
    return v;
}
__device__ __forceinline__ int warpSumi(int v) {
#pragma unroll
    for (int o = 16; o > 0; o >>= 1)
        v += __shfl_xor_sync(0xffffffffu, v, o);
    return v;
}

// ---------------------------------------------------------------------------
// GEMM: logits[r*32+k] = sum_d V[r,d]*W[k,d] + bias[k]
// 256 threads / 8 warps, 16 rows per warp (128 rows/block), D chunks of 16,
// 4-stage cp.async pipeline, ONE barrier per chunk, packed fma.rn.f32x2.
// ---------------------------------------------------------------------------
#define GR 16            // rows per warp
#define GD 16            // d per chunk
#define GNCH (DD/GD)     // 64 chunks
#define GSTG 4

__global__ __launch_bounds__(256, 3) void gemm_kernel(
    const float* __restrict__ V, const float* __restrict__ W,
    const float* __restrict__ bias, float* __restrict__ out,
    float* __restrict__ outAligned, int dualStore)
{
    __shared__ __align__(16) float Vs[GSTG][128][GD];
    __shared__ __align__(16) float Ws[GSTG][32][20];   // stride 20: odd*4 -> conflict-free

    const int tid  = threadIdx.x;
    const int warp = tid >> 5;
    const int lane = tid & 31;
    const int rowBase = blockIdx.x * 128;

    ull acc[GR];
#pragma unroll
    for (int r = 0; r < GR; r++) acc[r] = 0ull;

    auto loadChunk = [&](int st, int c) {
        const int d0 = c * GD;
        // V: 128 rows x 16 floats = 512 float4 -> 2 per thread
#pragma unroll
        for (int p = 0; p < 2; p++) {
            int idx = p * 256 + tid;
            int r = idx >> 2, c4 = idx & 3;
            cpa16(&Vs[st][r][c4 * 4], &V[(size_t)(rowBase + r) * DD + d0 + c4 * 4]);
        }
        // W: 32 k x 16 floats = 128 float4 -> threads 0..127
        if (tid < 128) {
            int k = tid >> 2, c4 = tid & 3;
            cpa16(&Ws[st][k][c4 * 4], &W[(size_t)k * DD + d0 + c4 * 4]);
        }
        cpa_commit();
    };

    loadChunk(0, 0);
    loadChunk(1, 1);
    loadChunk(2, 2);

    for (int c = 0; c < GNCH; c++) {
        cpa_wait<2>();          // group c complete
        __syncthreads();        // all threads' waits passed; buf (c-1)&3 free
        if (c + 3 < GNCH) loadChunk((c + 3) & 3, c + 3);
        const int st = c & 3;

#pragma unroll
        for (int g = 0; g < 4; g++) {                 // dd = 4*g
            ulonglong2 wv = *(const ulonglong2*)&Ws[st][lane][g * 4];
#pragma unroll
            for (int r = 0; r < GR; r++) {
                ulonglong2 vv = *(const ulonglong2*)&Vs[st][warp * GR + r][g * 4];
                acc[r] = fma2(vv.x, wv.x, acc[r]);
                acc[r] = fma2(vv.y, wv.y, acc[r]);
            }
        }
    }

    const float bk = bias[lane];
#pragma unroll
    for (int r = 0; r < GR; r++) {
        float2 f = unpack2(acc[r]);
        float val = f.x + f.y + bk;
        size_t idx = (size_t)(rowBase + warp * GR + r) * KK + lane;
        outAligned[idx] = val;
        if (dualStore) out[idx] = val;
    }
}

// ---------------------------------------------------------------------------
// CRF forward + gold-path score. One warp per batch; lane j = state j.
// Scaled-probability recurrence. Per step: STS a -> syncwarp -> 8x LDS.128 of
// a-vector -> 16 packed FFMA2 dot -> masked update. Per chunk (16 steps):
// single chunk max, lazy exp, popcount-based cl, one renorm.
// ---------------------------------------------------------------------------
__global__ __launch_bounds__(32) void crf_kernel(
    const float* __restrict__ L,       // logits [B,T,K] (16B aligned)
    const int*   __restrict__ mask,    // [B,T]
    const int*   __restrict__ targets, // [B,T]
    const float* __restrict__ trans,   // [K,K]
    const float* __restrict__ startT,  // [K]
    const float* __restrict__ endT)    // [K]
{
    __shared__ __align__(16) float Ls[2][16 * 32];   // 2 x 2KB logits staging
    __shared__ __align__(16) float a_sh[2][32];      // double-buffered alpha

    const int b = blockIdx.x;
    const int j = threadIdx.x;
    const unsigned FULL = 0xffffffffu;

    // packed E column j: ep[p] = (exp(trans[2p][j]), exp(trans[2p+1][j]))
    ull ep[16];
#pragma unroll
    for (int p = 0; p < 16; p++) {
        float e0 = __expf(trans[(2 * p) * KK + j]);
        float e1 = __expf(trans[(2 * p + 1) * KK + j]);
        ep[p] = pack2(e0, e1);
    }

    const float* Lb = L + (size_t)b * TT * KK;
    const int*   mb = mask + (size_t)b * TT;

    // mask bits, replicated per lane via ballot
    unsigned mbits[16];
#pragma unroll
    for (int w = 0; w < 16; w++)
        mbits[w] = __ballot_sync(FULL, mb[w * 32 + j] != 0);

    auto loadChunk = [&](int buf, int c) {
        const float* src = Lb + (size_t)c * 16 * KK;
#pragma unroll
        for (int q = 0; q < 4; q++) {
            int idx = q * 32 + j;
            cpa16(&Ls[buf][idx * 4], src + idx * 4);
        }
        cpa_commit();
    };

    loadChunk(0, 0);
    loadChunk(1, 1);

    float a = 0.f, cl = 0.f;
    int abuf = 0;

    for (int c = 0; c < 32; c++) {
        cpa_wait<1>();
        __syncwarp();

        // read chunk logits, single chunk max
        float lg[16];
#pragma unroll
        for (int s = 0; s < 16; s++) lg[s] = Ls[c & 1][s * 32 + j];
        float mc = lg[0];
#pragma unroll
        for (int s = 1; s < 16; s++) mc = fmaxf(mc, lg[s]);
        mc = warpMaxf(mc);
        __syncwarp();
        if (c + 2 < 32) loadChunk(c & 1, c + 2);

        unsigned bits = (mbits[c >> 1] >> ((c & 1) * 16)) & 0xFFFFu;

        if (c == 0) {
            // init t = 0
            float s0v = startT[j] + lg[0];
            float mm = warpMaxf(s0v);
            a  = __expf(s0v - mm);
            cl = mm;
            a_sh[0][j] = a;
            abuf = 0;
        }

#pragma unroll
        for (int s = 0; s < 16; s++) {
            if (c == 0 && s == 0) continue;          // uniform, handled above
            __syncwarp();                            // prev STS visible
            float gg = __expf(lg[s] - mc);           // issued early, used late
            const ulonglong2* ap = (const ulonglong2*)a_sh[abuf];
            ull p0 = 0, p1 = 0, p2 = 0, p3 = 0;
#pragma unroll
            for (int i = 0; i < 8; i += 4) {
                ulonglong2 q0 = ap[i + 0];
                ulonglong2 q1 = ap[i + 1];
                ulonglong2 q2 = ap[i + 2];
                ulonglong2 q3 = ap[i + 3];
                p0 = fma2(q0.x, ep[2 * i + 0], p0);
                p0 = fma2(q0.y, ep[2 * i + 1], p0);
                p1 = fma2(q1.x, ep[2 * i + 2], p1);
                p1 = fma2(q1.y, ep[2 * i + 3], p1);
                p2 = fma2(q2.x, ep[2 * i + 4], p2);
                p2 = fma2(q2.y, ep[2 * i + 5], p2);
                p3 = fma2(q3.x, ep[2 * i + 6], p3);
                p3 = fma2(q3.y, ep[2 * i + 7], p3);
            }
            ull t = add2(add2(p0, p1), add2(p2, p3));
            float2 f = unpack2(t);
            float dot = f.x + f.y;
            if ((bits >> s) & 1u) a = dot * gg;
            a_sh[abuf ^ 1][j] = a;
            abuf ^= 1;
        }

        // cl accumulation: mc added once per masked-in step of this chunk
        unsigned effb = (c == 0) ? (bits & 0xFFFEu) : bits;
        cl += mc * (float)__popc(effb);

        // renorm once per chunk
        float Mx = warpMaxf(a);
        a = __fdividef(a, Mx);
        cl += __logf(Mx);
        a_sh[abuf][j] = a;       // own slot rewrite; visible after next syncwarp
    }

    // partition = cl + log(sum_j a_j * exp(end_j))
    float pe = a * __expf(endT[j]);
    float S  = warpSumf(pe);
    float partition = cl + __logf(S);

    // ---- gold path score ----
    float emit_s = 0.f, trans_s = 0.f;
    int msum = 0;
    for (int t = j; t < TT; t += 32) {
        int tg = targets[(size_t)b * TT + t];
        int mk = mb[t];
        float em = Lb[(size_t)t * KK + tg];
        emit_s += em * (float)mk;
        if (t >= 1) {
            int tgp = targets[(size_t)b * TT + t - 1];
            trans_s += trans[tgp * KK + tg] * (float)mk;
        }
        msum += mk;
    }
    emit_s  = warpSumf(emit_s);
    trans_s = warpSumf(trans_s);
    msum    = warpSumi(msum);

    if (j == 0) {
        int last = msum - 1;
        int t0 = targets[(size_t)b * TT];
        int tl = targets[(size_t)b * TT + last];
        float score = startT[t0] + emit_s + trans_s + endT[tl];
        g_spart[b] = score - partition;
        g_msum[b]  = msum;
    }
}

// ---------------------------------------------------------------------------
__global__ __launch_bounds__(32) void finish_kernel(float* __restrict__ out,
                                                    int writeLoss)
{
    const int j = threadIdx.x;
    float sp = g_spart[j] + g_spart[j + 32];
    int   ms = g_msum[j]  + g_msum[j + 32];
    sp = warpSumf(sp);
    ms = warpSumi(ms);
    if (j == 0 && writeLoss) out[0] = -sp / (float)ms;
}

// ---------------------------------------------------------------------------
extern "C" void kernel_launch(void* const* d_in, const int* in_sizes, int n_in,
                              void* d_out, int out_size)
{
    const float* V       = (const float*)d_in[0];
    const int*   mask    = (const int*)  d_in[1];
    const int*   targets = (const int*)  d_in[2];
    const float* W       = (const float*)d_in[3];
    const float* bias    = (const float*)d_in[4];
    const float* trans   = (const float*)d_in[5];
    const float* startT  = (const float*)d_in[6];
    const float* endT    = (const float*)d_in[7];
    float* out = (float*)d_out;

    void* p = nullptr;
    cudaGetSymbolAddress(&p, g_scratch_logits);
    float* scratch = (float*)p;

    const int loff = out_size - BTK;   // (loss, logits) concat
    float* outLogits;
    int dualStore;
    if (loff >= 0) {
        outLogits = out + loff;
        if ((((uintptr_t)outLogits) & 15u) == 0) {
            scratch = outLogits;            // aligned: single store stream
            dualStore = 0;
        } else {
            dualStore = 1;                  // unaligned: scratch + harness copy
        }
    } else {
        outLogits = scratch;
        dualStore = 0;
    }

    gemm_kernel<<<(BB * TT) / 128, 256>>>(V, W, bias, outLogits, scratch, dualStore);
    crf_kernel<<<BB, 32>>>(scratch, mask, targets, trans, startT, endT);
    finish_kernel<<<1, 32>>>(out, (loff >= 1) ? 1 : 0);
}